// round 1
// baseline (speedup 1.0000x reference)
#include <cuda_runtime.h>
#include <math.h>

// Problem constants
#define BNUM 8
#define TNUM 1024
#define CDIM 512
#define EDIM 256
#define HNUM 8
#define BT   8192          // B*T
#define QKV_LD 6144        // Q|K|V concatenated per token row
#define HE   2048          // H*E

// Scratch (allocation-free rule: __device__ globals)
__device__ float g_qkv[(long)BT * QKV_LD];              // [8192, 6144]  Q|K|V
__device__ float g_S[(long)BNUM * HNUM * TNUM * TNUM];  // [64, 1024, 1024]
__device__ float g_O[(long)BT * HE];                    // [8192, 2048]

// ---------------------------------------------------------------------------
// Generic 128x128x8 fp32 tiled GEMM, 8x8 microtile, 256 threads.
//   C = A * B    (TRANSB=false: B is K x N row-major)
//   C = A * B^T  (TRANSB=true : B is N x K row-major)
// Batched over blockIdx.z with (b,h) decomposed strides.
// EPI 0: C[row*ldc+col] = acc * (col<scaleCols ? scale : 1)
// EPI 1: out[row*512 + 256 + col] = acc + bu[col] + x[row*512 + 256 + col]
// All of M,N divisible by 128; K divisible by 8. No bounds checks.
// ---------------------------------------------------------------------------
template<int EPI, bool TRANSB>
__global__ void __launch_bounds__(256)
gemm128(const float* __restrict__ A, const float* __restrict__ B,
        float* __restrict__ C,
        int K, int lda, int ldb, int ldc,
        int Hdiv, long sAb, long sAh, long sBb, long sBh, long sCb, long sCh,
        const float* __restrict__ xin, const float* __restrict__ bu,
        float scale, int scaleCols)
{
    constexpr int BM = 128, BN = 128, BK = 8, TM = 8, TN = 8;
    __shared__ float As[BK][BM];
    __shared__ float Bs[BK][BN];

    const int z  = blockIdx.z;
    const int zb = z / Hdiv;
    const int zh = z % Hdiv;
    A += zb * sAb + zh * sAh;
    B += zb * sBb + zh * sBh;
    C += zb * sCb + zh * sCh;

    const int mBase = blockIdx.y * BM;
    const int nBase = blockIdx.x * BN;
    const int tid   = threadIdx.x;

    // A tile load mapping: 128 rows x 8 k, 4 floats/thread (float4)
    const int aRow = tid >> 1;          // 0..127
    const int aCol = (tid & 1) * 4;     // 0 or 4
    // B tile load mapping
    const int bRowNN = tid >> 5;        // 0..7   (k)
    const int bColNN = (tid & 31) * 4;  // 0..124 (n)
    const int bRowNT = tid >> 1;        // 0..127 (n)
    const int bColNT = (tid & 1) * 4;   // 0 or 4 (k)

    const int tRow = (tid >> 4) * TM;   // 0..120
    const int tCol = (tid & 15) * TN;   // 0..120

    float acc[TM][TN];
    #pragma unroll
    for (int i = 0; i < TM; i++)
        #pragma unroll
        for (int j = 0; j < TN; j++) acc[i][j] = 0.f;

    for (int k0 = 0; k0 < K; k0 += BK) {
        // load A tile (transposed into As[k][m])
        float4 av = *reinterpret_cast<const float4*>(
            &A[(long)(mBase + aRow) * lda + k0 + aCol]);
        As[aCol + 0][aRow] = av.x;
        As[aCol + 1][aRow] = av.y;
        As[aCol + 2][aRow] = av.z;
        As[aCol + 3][aRow] = av.w;

        if (TRANSB) {
            float4 bv = *reinterpret_cast<const float4*>(
                &B[(long)(nBase + bRowNT) * ldb + k0 + bColNT]);
            Bs[bColNT + 0][bRowNT] = bv.x;
            Bs[bColNT + 1][bRowNT] = bv.y;
            Bs[bColNT + 2][bRowNT] = bv.z;
            Bs[bColNT + 3][bRowNT] = bv.w;
        } else {
            float4 bv = *reinterpret_cast<const float4*>(
                &B[(long)(k0 + bRowNN) * ldb + nBase + bColNN]);
            *reinterpret_cast<float4*>(&Bs[bRowNN][bColNN]) = bv;
        }
        __syncthreads();

        #pragma unroll
        for (int kk = 0; kk < BK; kk++) {
            float ar[TM], br[TN];
            #pragma unroll
            for (int i = 0; i < TM; i += 4)
                *reinterpret_cast<float4*>(&ar[i]) =
                    *reinterpret_cast<const float4*>(&As[kk][tRow + i]);
            #pragma unroll
            for (int j = 0; j < TN; j += 4)
                *reinterpret_cast<float4*>(&br[j]) =
                    *reinterpret_cast<const float4*>(&Bs[kk][tCol + j]);
            #pragma unroll
            for (int i = 0; i < TM; i++)
                #pragma unroll
                for (int j = 0; j < TN; j++)
                    acc[i][j] = fmaf(ar[i], br[j], acc[i][j]);
        }
        __syncthreads();
    }

    if (EPI == 0) {
        #pragma unroll
        for (int i = 0; i < TM; i++) {
            const long rowOff = (long)(mBase + tRow + i) * ldc;
            #pragma unroll
            for (int j = 0; j < TN; j++) {
                const int col = nBase + tCol + j;
                float v = acc[i][j];
                if (col < scaleCols) v *= scale;
                C[rowOff + col] = v;
            }
        }
    } else {
        #pragma unroll
        for (int i = 0; i < TM; i++) {
            const int r = mBase + tRow + i;
            #pragma unroll
            for (int j = 0; j < TN; j++) {
                const int c = nBase + tCol + j;
                C[(long)r * CDIM + EDIM + c] =
                    acc[i][j] + bu[c] + xin[(long)r * CDIM + EDIM + c];
            }
        }
    }
}

// ---------------------------------------------------------------------------
// Row softmax over rows of length 1024. One CTA (256 threads) per row.
// ---------------------------------------------------------------------------
__global__ void __launch_bounds__(256) softmax1024(float* __restrict__ S)
{
    float4* p4 = reinterpret_cast<float4*>(S + (size_t)blockIdx.x * 1024);
    const int tid  = threadIdx.x;
    const int lane = tid & 31;
    const int wid  = tid >> 5;
    __shared__ float smax[8];
    __shared__ float ssum[8];
    __shared__ float bcast[2];

    float4 v = p4[tid];
    float m = fmaxf(fmaxf(v.x, v.y), fmaxf(v.z, v.w));
    #pragma unroll
    for (int o = 16; o; o >>= 1) m = fmaxf(m, __shfl_xor_sync(~0u, m, o));
    if (lane == 0) smax[wid] = m;
    __syncthreads();
    if (tid == 0) {
        float bm = smax[0];
        #pragma unroll
        for (int i = 1; i < 8; i++) bm = fmaxf(bm, smax[i]);
        bcast[0] = bm;
    }
    __syncthreads();
    const float bm = bcast[0];

    float4 e;
    e.x = expf(v.x - bm); e.y = expf(v.y - bm);
    e.z = expf(v.z - bm); e.w = expf(v.w - bm);
    float s = e.x + e.y + e.z + e.w;
    #pragma unroll
    for (int o = 16; o; o >>= 1) s += __shfl_xor_sync(~0u, s, o);
    if (lane == 0) ssum[wid] = s;
    __syncthreads();
    if (tid == 0) {
        float bs = 0.f;
        #pragma unroll
        for (int i = 0; i < 8; i++) bs += ssum[i];
        bcast[1] = 1.f / bs;
    }
    __syncthreads();
    const float r = bcast[1];
    e.x *= r; e.y *= r; e.z *= r; e.w *= r;
    p4[tid] = e;
}

// ---------------------------------------------------------------------------
// Copy x1 (first 256 channels) into out's first half.
// ---------------------------------------------------------------------------
__global__ void __launch_bounds__(256) copy_x1(const float* __restrict__ x,
                                               float* __restrict__ out)
{
    const long idx = (long)blockIdx.x * blockDim.x + threadIdx.x; // over BT*64
    const long r  = idx >> 6;        // token row
    const long c4 = idx & 63;        // float4 col within x1
    const float4* x4 = reinterpret_cast<const float4*>(x);
    float4* o4 = reinterpret_cast<float4*>(out);
    o4[r * 128 + c4] = x4[r * 128 + c4];
}

// ---------------------------------------------------------------------------
extern "C" void kernel_launch(void* const* d_in, const int* in_sizes, int n_in,
                              void* d_out, int out_size)
{
    const float* x  = (const float*)d_in[0];
    const float* Wq = (const float*)d_in[1];
    const float* Wk = (const float*)d_in[2];
    const float* Wv = (const float*)d_in[3];
    const float* Wu = (const float*)d_in[4];
    const float* bu = (const float*)d_in[5];
    float* out = (float*)d_out;

    float *qkv, *S, *O;
    cudaGetSymbolAddress((void**)&qkv, g_qkv);
    cudaGetSymbolAddress((void**)&S,   g_S);
    cudaGetSymbolAddress((void**)&O,   g_O);

    const dim3 blk(256);
    const float sc = 0.25f; // E^-0.25 = 256^-0.25

    // 1) Q = x1 @ Wq^T * sc ; K = x1 @ Wk^T * sc ; V = x1 @ Wv^T
    //    x1: rows of x, lda=512, first 256 cols. Out into g_qkv columns.
    {
        dim3 g(HE / 128, BT / 128, 1);
        gemm128<0, true><<<g, blk>>>(x, Wq, qkv,           EDIM, CDIM, EDIM, QKV_LD,
                                     1, 0, 0, 0, 0, 0, 0, nullptr, nullptr, sc, HE);
        gemm128<0, true><<<g, blk>>>(x, Wk, qkv + HE,      EDIM, CDIM, EDIM, QKV_LD,
                                     1, 0, 0, 0, 0, 0, 0, nullptr, nullptr, sc, HE);
        gemm128<0, true><<<g, blk>>>(x, Wv, qkv + 2 * HE,  EDIM, CDIM, EDIM, QKV_LD,
                                     1, 0, 0, 0, 0, 0, 0, nullptr, nullptr, 1.f, 0);
    }

    // 2) S[b,h] = Q[b,:,h,:] @ K[b,:,h,:]^T   (1024x1024x256 per z, z = b*8+h)
    {
        dim3 g(TNUM / 128, TNUM / 128, BNUM * HNUM);
        gemm128<0, true><<<g, blk>>>(
            qkv, qkv + HE, S, EDIM, QKV_LD, QKV_LD, TNUM,
            HNUM,
            (long)TNUM * QKV_LD, (long)EDIM,          // A strides (b,h)
            (long)TNUM * QKV_LD, (long)EDIM,          // B strides (b,h)
            (long)HNUM * TNUM * TNUM, (long)TNUM * TNUM, // C strides (b,h)
            nullptr, nullptr, 1.f, 0);
    }

    // 3) softmax over last axis of S (65536 rows of 1024)
    softmax1024<<<BNUM * HNUM * TNUM, 256>>>(S);

    // 4) O[b,:,h,:] = P[b,h] @ V[b,:,h,:]   (1024x256x1024 per z, NN)
    {
        dim3 g(EDIM / 128, TNUM / 128, BNUM * HNUM);
        gemm128<0, false><<<g, blk>>>(
            S, qkv + 2 * HE, O, TNUM, TNUM, QKV_LD, HE,
            HNUM,
            (long)HNUM * TNUM * TNUM, (long)TNUM * TNUM, // A strides (b,h)
            (long)TNUM * QKV_LD, (long)EDIM,             // B strides (b,h)
            (long)TNUM * HE, (long)EDIM,                 // C strides (b,h)
            nullptr, nullptr, 1.f, 0);
    }

    // 5) out[:, 256:] = O @ Wu^T + bu + x2 ;  (8192 x 256 x 2048, NT)
    {
        dim3 g(EDIM / 128, BT / 128, 1);
        gemm128<1, true><<<g, blk>>>(O, Wu, out, HE, HE, HE, CDIM,
                                     1, 0, 0, 0, 0, 0, 0, x, bu, 1.f, 0);
    }

    // 6) out[:, :256] = x1
    copy_x1<<<(BT * 64) / 256, 256>>>(x, out);
}

// round 2
// speedup vs baseline: 4.1890x; 4.1890x over previous
#include <cuda_runtime.h>
#include <cuda_bf16.h>
#include <math.h>
#include <stdint.h>

// Problem constants
#define BNUM 8
#define TNUM 1024
#define CDIM 512
#define EDIM 256
#define HNUM 8
#define BT   8192
#define QKV_LD 6144
#define HE   2048

typedef __nv_bfloat16 bf16;
typedef __nv_bfloat162 bf162;

// Scratch (__device__ globals; no allocation allowed)
__device__ bf16  g_x1b[(long)BT * EDIM];                 // x1 in bf16
__device__ bf16  g_Wcat[(long)QKV_LD * EDIM];            // Wq*0.25 | Wk*0.25 | Wv
__device__ bf16  g_Wub[(long)EDIM * HE];                 // Wu bf16
__device__ bf16  g_qkv[(long)BT * QKV_LD];               // Q|K|V bf16
__device__ float g_S[(long)BNUM * HNUM * TNUM * TNUM];   // logits fp32
__device__ bf16  g_P[(long)BNUM * HNUM * TNUM * TNUM];   // softmax bf16
__device__ bf16  g_O[(long)BT * HE];                     // attention out bf16

__device__ __forceinline__ uint32_t sptr(const void* p) {
    return (uint32_t)__cvta_generic_to_shared(p);
}
__device__ __forceinline__ void ldm_x4(uint32_t& r0, uint32_t& r1, uint32_t& r2,
                                       uint32_t& r3, uint32_t addr) {
    asm volatile("ldmatrix.sync.aligned.m8n8.x4.shared.b16 {%0,%1,%2,%3}, [%4];"
                 : "=r"(r0), "=r"(r1), "=r"(r2), "=r"(r3) : "r"(addr));
}
__device__ __forceinline__ void ldm_x4_t(uint32_t& r0, uint32_t& r1, uint32_t& r2,
                                         uint32_t& r3, uint32_t addr) {
    asm volatile("ldmatrix.sync.aligned.m8n8.x4.trans.shared.b16 {%0,%1,%2,%3}, [%4];"
                 : "=r"(r0), "=r"(r1), "=r"(r2), "=r"(r3) : "r"(addr));
}
__device__ __forceinline__ void mma16816(float* d, const uint32_t* a, const uint32_t* b) {
    asm volatile(
        "mma.sync.aligned.m16n8k16.row.col.f32.bf16.bf16.f32 "
        "{%0,%1,%2,%3}, {%4,%5,%6,%7}, {%8,%9}, {%0,%1,%2,%3};"
        : "+f"(d[0]), "+f"(d[1]), "+f"(d[2]), "+f"(d[3])
        : "r"(a[0]), "r"(a[1]), "r"(a[2]), "r"(a[3]), "r"(b[0]), "r"(b[1]));
}

// ---------------------------------------------------------------------------
// bf16 tensor-core GEMM: 128x128 tile, BK=32, 256 threads (8 warps, 32x64 each).
//   TRANSB=true : C = A * B^T  (B stored [N][K], K contiguous)
//   TRANSB=false: C = A * B    (B stored [K][N], N contiguous)
// EPI 0: C bf16 at C[row*ldc+col]
// EPI 1: C fp32 at C[row*ldc+col]
// EPI 2: out[row*512+256+col] = acc + bu[col] + xin[row*512+256+col] (fp32)
// M,N multiples of 128, K multiple of 32, all pointers 16B aligned.
// ---------------------------------------------------------------------------
template<int EPI, bool TRANSB>
__global__ void __launch_bounds__(256)
gemm_bf16(const bf16* __restrict__ A, const bf16* __restrict__ B,
          void* __restrict__ Cv,
          int K, int lda, int ldb, int ldc,
          int Hdiv, long sAb, long sAh, long sBb, long sBh, long sCb, long sCh,
          const float* __restrict__ xin, const float* __restrict__ bu)
{
    constexpr int APAD = 40;              // bf16 row stride for A / NT-B tiles
    constexpr int BPADNN = 136;           // bf16 row stride for NN-B tiles
    __shared__ __align__(16) bf16 As[128 * APAD];
    __shared__ __align__(16) bf16 Bs[TRANSB ? 128 * APAD : 32 * BPADNN];

    const int z  = blockIdx.z;
    const int zb = z / Hdiv;
    const int zh = z % Hdiv;
    A += zb * sAb + zh * sAh;
    B += zb * sBb + zh * sBh;

    const int mBase = blockIdx.y * 128;
    const int nBase = blockIdx.x * 128;
    const int tid   = threadIdx.x;
    const int lane  = tid & 31;
    const int warp  = tid >> 5;
    const int warpM = (warp & 3) * 32;    // 4 warps along M
    const int warpN = (warp >> 2) * 64;   // 2 warps along N

    // gmem->smem mapping (uint4 = 8 bf16). A tile: 128x32 -> 512 uint4.
    const int aRow = tid >> 1;                 // 0..127 (u = tid: row=u/4? see below)
    // use linear u over 512: row = u>>2, chunk = u&3
    // B NN tile: 32x128 -> 512 uint4: row = u>>4, chunk = u&15

    // ldmatrix per-lane offsets
    const int lj = lane >> 3;        // matrix index 0..3
    const int lr = lane & 7;
    // A frag: row = (lj&1)*8 + lr, col = (lj>>1)*8
    const int aFR = (lj & 1) * 8 + lr;
    const int aFC = (lj >> 1) * 8;
    // B NT frag: n = lr + 8*(lj>>1), k = 8*(lj&1)
    const int bNTn = lr + 8 * (lj >> 1);
    const int bNTk = 8 * (lj & 1);
    // B NN frag (trans): k = lr + 8*(lj&1), n = 8*(lj>>1)
    const int bNNk = lr + 8 * (lj & 1);
    const int bNNn = 8 * (lj >> 1);

    const uint32_t sA = sptr(As);
    const uint32_t sB = sptr(Bs);

    float acc[2][8][4];
    #pragma unroll
    for (int i = 0; i < 2; i++)
        #pragma unroll
        for (int j = 0; j < 8; j++)
            #pragma unroll
            for (int q = 0; q < 4; q++) acc[i][j][q] = 0.f;

    for (int k0 = 0; k0 < K; k0 += 32) {
        // ---- gmem loads to registers ----
        uint4 av0, av1, bv0, bv1;
        {
            int u0 = tid, u1 = tid + 256;
            int r0 = u0 >> 2, c0 = (u0 & 3) * 8;
            int r1 = u1 >> 2, c1 = (u1 & 3) * 8;
            av0 = *reinterpret_cast<const uint4*>(&A[(long)(mBase + r0) * lda + k0 + c0]);
            av1 = *reinterpret_cast<const uint4*>(&A[(long)(mBase + r1) * lda + k0 + c1]);
            if (TRANSB) {
                bv0 = *reinterpret_cast<const uint4*>(&B[(long)(nBase + r0) * ldb + k0 + c0]);
                bv1 = *reinterpret_cast<const uint4*>(&B[(long)(nBase + r1) * ldb + k0 + c1]);
            } else {
                int br0 = u0 >> 4, bc0 = (u0 & 15) * 8;
                int br1 = u1 >> 4, bc1 = (u1 & 15) * 8;
                bv0 = *reinterpret_cast<const uint4*>(&B[(long)(k0 + br0) * ldb + nBase + bc0]);
                bv1 = *reinterpret_cast<const uint4*>(&B[(long)(k0 + br1) * ldb + nBase + bc1]);
            }
        }
        __syncthreads();
        {
            int u0 = tid, u1 = tid + 256;
            int r0 = u0 >> 2, c0 = (u0 & 3) * 8;
            int r1 = u1 >> 2, c1 = (u1 & 3) * 8;
            *reinterpret_cast<uint4*>(&As[r0 * APAD + c0]) = av0;
            *reinterpret_cast<uint4*>(&As[r1 * APAD + c1]) = av1;
            if (TRANSB) {
                *reinterpret_cast<uint4*>(&Bs[r0 * APAD + c0]) = bv0;
                *reinterpret_cast<uint4*>(&Bs[r1 * APAD + c1]) = bv1;
            } else {
                int br0 = u0 >> 4, bc0 = (u0 & 15) * 8;
                int br1 = u1 >> 4, bc1 = (u1 & 15) * 8;
                *reinterpret_cast<uint4*>(&Bs[br0 * BPADNN + bc0]) = bv0;
                *reinterpret_cast<uint4*>(&Bs[br1 * BPADNN + bc1]) = bv1;
            }
        }
        __syncthreads();

        #pragma unroll
        for (int kk = 0; kk < 32; kk += 16) {
            uint32_t aF[2][4];
            #pragma unroll
            for (int mt = 0; mt < 2; mt++) {
                uint32_t addr = sA + ((warpM + mt * 16 + aFR) * APAD + kk + aFC) * 2;
                ldm_x4(aF[mt][0], aF[mt][1], aF[mt][2], aF[mt][3], addr);
            }
            uint32_t bF[8][2];
            #pragma unroll
            for (int np = 0; np < 4; np++) {
                uint32_t r0, r1, r2, r3;
                if (TRANSB) {
                    uint32_t addr = sB + ((warpN + np * 16 + bNTn) * APAD + kk + bNTk) * 2;
                    ldm_x4(r0, r1, r2, r3, addr);
                } else {
                    uint32_t addr = sB + ((kk + bNNk) * BPADNN + warpN + np * 16 + bNNn) * 2;
                    ldm_x4_t(r0, r1, r2, r3, addr);
                }
                bF[np * 2][0] = r0; bF[np * 2][1] = r1;
                bF[np * 2 + 1][0] = r2; bF[np * 2 + 1][1] = r3;
            }
            #pragma unroll
            for (int mt = 0; mt < 2; mt++)
                #pragma unroll
                for (int nt = 0; nt < 8; nt++)
                    mma16816(acc[mt][nt], aF[mt], bF[nt]);
        }
    }

    // ---- epilogue ----
    const int qr = lane >> 2;
    const int qc = (lane & 3) * 2;
    #pragma unroll
    for (int mt = 0; mt < 2; mt++) {
        #pragma unroll
        for (int nt = 0; nt < 8; nt++) {
            int r0 = mBase + warpM + mt * 16 + qr;
            int r1 = r0 + 8;
            int col = nBase + warpN + nt * 8 + qc;
            float* c = acc[mt][nt];
            if (EPI == 0) {
                bf16* C = (bf16*)Cv + zb * sCb + zh * sCh;
                *reinterpret_cast<bf162*>(&C[(long)r0 * ldc + col]) =
                    __floats2bfloat162_rn(c[0], c[1]);
                *reinterpret_cast<bf162*>(&C[(long)r1 * ldc + col]) =
                    __floats2bfloat162_rn(c[2], c[3]);
            } else if (EPI == 1) {
                float* C = (float*)Cv + zb * sCb + zh * sCh;
                *reinterpret_cast<float2*>(&C[(long)r0 * ldc + col]) = make_float2(c[0], c[1]);
                *reinterpret_cast<float2*>(&C[(long)r1 * ldc + col]) = make_float2(c[2], c[3]);
            } else {
                float* C = (float*)Cv;
                float b0 = bu[col], b1 = bu[col + 1];
                long o0 = (long)r0 * CDIM + EDIM + col;
                long o1 = (long)r1 * CDIM + EDIM + col;
                C[o0]     = c[0] + b0 + xin[o0];
                C[o0 + 1] = c[1] + b1 + xin[o0 + 1];
                C[o1]     = c[2] + b0 + xin[o1];
                C[o1 + 1] = c[3] + b1 + xin[o1 + 1];
            }
        }
    }
}

// ---------------------------------------------------------------------------
// Row softmax (1024 wide, fp32 in, bf16 out). One CTA of 256 per row.
// ---------------------------------------------------------------------------
__global__ void __launch_bounds__(256)
softmax1024(const float* __restrict__ S, bf16* __restrict__ P)
{
    const float4* p4 = reinterpret_cast<const float4*>(S + (size_t)blockIdx.x * 1024);
    bf162* o2 = reinterpret_cast<bf162*>(P + (size_t)blockIdx.x * 1024);
    const int tid = threadIdx.x, lane = tid & 31, wid = tid >> 5;
    __shared__ float red[8];
    __shared__ float bcast[2];

    float4 v = p4[tid];
    float m = fmaxf(fmaxf(v.x, v.y), fmaxf(v.z, v.w));
    #pragma unroll
    for (int o = 16; o; o >>= 1) m = fmaxf(m, __shfl_xor_sync(~0u, m, o));
    if (lane == 0) red[wid] = m;
    __syncthreads();
    if (tid == 0) {
        float bm = red[0];
        #pragma unroll
        for (int i = 1; i < 8; i++) bm = fmaxf(bm, red[i]);
        bcast[0] = bm;
    }
    __syncthreads();
    const float bm = bcast[0];

    float4 e;
    e.x = __expf(v.x - bm); e.y = __expf(v.y - bm);
    e.z = __expf(v.z - bm); e.w = __expf(v.w - bm);
    float s = e.x + e.y + e.z + e.w;
    #pragma unroll
    for (int o = 16; o; o >>= 1) s += __shfl_xor_sync(~0u, s, o);
    if (lane == 0) red[wid] = s;
    __syncthreads();
    if (tid == 0) {
        float bs = 0.f;
        #pragma unroll
        for (int i = 0; i < 8; i++) bs += red[i];
        bcast[1] = 1.f / bs;
    }
    __syncthreads();
    const float r = bcast[1];
    o2[tid * 2]     = __floats2bfloat162_rn(e.x * r, e.y * r);
    o2[tid * 2 + 1] = __floats2bfloat162_rn(e.z * r, e.w * r);
}

// ---------------------------------------------------------------------------
// Conversions
// ---------------------------------------------------------------------------
__global__ void __launch_bounds__(256)
conv_x1(const float* __restrict__ x, bf16* __restrict__ dst)
{
    long idx = (long)blockIdx.x * 256 + threadIdx.x;   // over BT*64
    long row = idx >> 6;
    int  c4  = (int)(idx & 63) * 4;
    float4 v = *reinterpret_cast<const float4*>(&x[row * CDIM + c4]);
    bf162* d = reinterpret_cast<bf162*>(&dst[row * EDIM + c4]);
    d[0] = __floats2bfloat162_rn(v.x, v.y);
    d[1] = __floats2bfloat162_rn(v.z, v.w);
}

__global__ void __launch_bounds__(256)
conv_wcat(const float* __restrict__ Wq, const float* __restrict__ Wk,
          const float* __restrict__ Wv, bf16* __restrict__ dst)
{
    long idx = (long)blockIdx.x * 256 + threadIdx.x;   // over 6144*64
    long row = idx >> 6;
    int  c4  = (int)(idx & 63) * 4;
    const float* src; float s;
    if (row < 2048)      { src = Wq + row * EDIM;          s = 0.25f; }
    else if (row < 4096) { src = Wk + (row - 2048) * EDIM; s = 0.25f; }
    else                 { src = Wv + (row - 4096) * EDIM; s = 1.0f;  }
    float4 v = *reinterpret_cast<const float4*>(&src[c4]);
    bf162* d = reinterpret_cast<bf162*>(&dst[row * EDIM + c4]);
    d[0] = __floats2bfloat162_rn(v.x * s, v.y * s);
    d[1] = __floats2bfloat162_rn(v.z * s, v.w * s);
}

__global__ void __launch_bounds__(256)
conv_wu(const float* __restrict__ Wu, bf16* __restrict__ dst)
{
    long idx = (long)blockIdx.x * 256 + threadIdx.x;   // over 256*512
    long row = idx >> 9;
    int  c4  = (int)(idx & 511) * 4;
    float4 v = *reinterpret_cast<const float4*>(&Wu[row * HE + c4]);
    bf162* d = reinterpret_cast<bf162*>(&dst[row * HE + c4]);
    d[0] = __floats2bfloat162_rn(v.x, v.y);
    d[1] = __floats2bfloat162_rn(v.z, v.w);
}

__global__ void __launch_bounds__(256)
copy_x1(const float* __restrict__ x, float* __restrict__ out)
{
    const long idx = (long)blockIdx.x * blockDim.x + threadIdx.x; // over BT*64
    const long r  = idx >> 6;
    const long c4 = idx & 63;
    const float4* x4 = reinterpret_cast<const float4*>(x);
    float4* o4 = reinterpret_cast<float4*>(out);
    o4[r * 128 + c4] = x4[r * 128 + c4];
}

// ---------------------------------------------------------------------------
extern "C" void kernel_launch(void* const* d_in, const int* in_sizes, int n_in,
                              void* d_out, int out_size)
{
    const float* x  = (const float*)d_in[0];
    const float* Wq = (const float*)d_in[1];
    const float* Wk = (const float*)d_in[2];
    const float* Wv = (const float*)d_in[3];
    const float* Wu = (const float*)d_in[4];
    const float* bu = (const float*)d_in[5];
    float* out = (float*)d_out;

    bf16 *x1b, *Wcat, *Wub, *qkv, *P, *O;
    float* S;
    cudaGetSymbolAddress((void**)&x1b,  g_x1b);
    cudaGetSymbolAddress((void**)&Wcat, g_Wcat);
    cudaGetSymbolAddress((void**)&Wub,  g_Wub);
    cudaGetSymbolAddress((void**)&qkv,  g_qkv);
    cudaGetSymbolAddress((void**)&S,    g_S);
    cudaGetSymbolAddress((void**)&P,    g_P);
    cudaGetSymbolAddress((void**)&O,    g_O);

    const dim3 blk(256);

    // 0) conversions (scale folded into Wq/Wk)
    conv_x1  <<<BT * 64 / 256, blk>>>(x, x1b);
    conv_wcat<<<QKV_LD * 64 / 256, blk>>>(Wq, Wk, Wv, Wcat);
    conv_wu  <<<EDIM * 512 / 256, blk>>>(Wu, Wub);

    // 1) QKV = x1b @ Wcat^T  -> bf16 [8192, 6144]
    {
        dim3 g(QKV_LD / 128, BT / 128, 1);
        gemm_bf16<0, true><<<g, blk>>>(x1b, Wcat, qkv, EDIM, EDIM, EDIM, QKV_LD,
                                       1, 0, 0, 0, 0, 0, 0, nullptr, nullptr);
    }
    // 2) S[b,h] = Q[b,:,h,:] @ K[b,:,h,:]^T  (fp32)
    {
        dim3 g(TNUM / 128, TNUM / 128, BNUM * HNUM);
        gemm_bf16<1, true><<<g, blk>>>(
            qkv, qkv + HE, S, EDIM, QKV_LD, QKV_LD, TNUM,
            HNUM,
            (long)TNUM * QKV_LD, (long)EDIM,
            (long)TNUM * QKV_LD, (long)EDIM,
            (long)HNUM * TNUM * TNUM, (long)TNUM * TNUM,
            nullptr, nullptr);
    }
    // 3) P = softmax(S) -> bf16
    softmax1024<<<BNUM * HNUM * TNUM, blk>>>(S, P);

    // 4) O[b,:,h,:] = P[b,h] @ V[b,:,h,:]  (NN, bf16)
    {
        dim3 g(EDIM / 128, TNUM / 128, BNUM * HNUM);
        gemm_bf16<0, false><<<g, blk>>>(
            P, qkv + 2 * HE, O, TNUM, TNUM, QKV_LD, HE,
            HNUM,
            (long)HNUM * TNUM * TNUM, (long)TNUM * TNUM,
            (long)TNUM * QKV_LD, (long)EDIM,
            (long)TNUM * HE, (long)EDIM,
            nullptr, nullptr);
    }
    // 5) out[:,256:] = O @ Wub^T + bu + x2
    {
        dim3 g(EDIM / 128, BT / 128, 1);
        gemm_bf16<2, true><<<g, blk>>>(O, Wub, out, HE, HE, HE, CDIM,
                                       1, 0, 0, 0, 0, 0, 0, x, bu);
    }
    // 6) out[:,:256] = x1
    copy_x1<<<BT * 64 / 256, blk>>>(x, out);
}

// round 4
// speedup vs baseline: 5.9679x; 1.4247x over previous
#include <cuda_runtime.h>
#include <cuda_bf16.h>
#include <math.h>
#include <stdint.h>

// Problem constants
#define BNUM 8
#define TNUM 1024
#define CDIM 512
#define EDIM 256
#define HNUM 8
#define BT   8192
#define QKV_LD 6144
#define HE   2048

typedef __nv_bfloat16 bf16;
typedef __nv_bfloat162 bf162;

// Scratch (__device__ globals; no allocation allowed)
__device__ bf16  g_x1b[(long)BT * EDIM];
__device__ bf16  g_Wcat[(long)QKV_LD * EDIM];
__device__ bf16  g_Wub[(long)EDIM * HE];
__device__ bf16  g_qkv[(long)BT * QKV_LD];
__device__ float g_S[(long)BNUM * HNUM * TNUM * TNUM];
__device__ bf16  g_P[(long)BNUM * HNUM * TNUM * TNUM];
__device__ bf16  g_O[(long)BT * HE];

__device__ __forceinline__ uint32_t sptr(const void* p) {
    return (uint32_t)__cvta_generic_to_shared(p);
}
__device__ __forceinline__ void ldm_x4(uint32_t& r0, uint32_t& r1, uint32_t& r2,
                                       uint32_t& r3, uint32_t addr) {
    asm volatile("ldmatrix.sync.aligned.m8n8.x4.shared.b16 {%0,%1,%2,%3}, [%4];"
                 : "=r"(r0), "=r"(r1), "=r"(r2), "=r"(r3) : "r"(addr));
}
__device__ __forceinline__ void ldm_x4_t(uint32_t& r0, uint32_t& r1, uint32_t& r2,
                                         uint32_t& r3, uint32_t addr) {
    asm volatile("ldmatrix.sync.aligned.m8n8.x4.trans.shared.b16 {%0,%1,%2,%3}, [%4];"
                 : "=r"(r0), "=r"(r1), "=r"(r2), "=r"(r3) : "r"(addr));
}
__device__ __forceinline__ void mma16816(float* d, const uint32_t* a, const uint32_t* b) {
    asm volatile(
        "mma.sync.aligned.m16n8k16.row.col.f32.bf16.bf16.f32 "
        "{%0,%1,%2,%3}, {%4,%5,%6,%7}, {%8,%9}, {%0,%1,%2,%3};"
        : "+f"(d[0]), "+f"(d[1]), "+f"(d[2]), "+f"(d[3])
        : "r"(a[0]), "r"(a[1]), "r"(a[2]), "r"(a[3]), "r"(b[0]), "r"(b[1]));
}
__device__ __forceinline__ void cp16(uint32_t saddr, const void* gptr) {
    asm volatile("cp.async.cg.shared.global [%0], [%1], 16;" :: "r"(saddr), "l"(gptr));
}
#define CP_COMMIT() asm volatile("cp.async.commit_group;")
#define CP_WAIT(N)  asm volatile("cp.async.wait_group %0;" :: "n"(N))

// ---------------------------------------------------------------------------
// bf16 tensor-core GEMM, 128x128 tile, BK=32, cp.async 3-stage pipeline,
// 256 threads (8 warps, 32x64 warp tiles), 2 CTAs/SM.
//   TRANSB=true : C = A * B^T  (B stored [N][K])
//   TRANSB=false: C = A * B    (B stored [K][N])
// EPI 0: bf16 out; EPI 1: fp32 out; EPI 2: fused residual+bias fp32 out.
// ---------------------------------------------------------------------------
#define NSTAGE 3

template<int EPI, bool TRANSB>
__global__ void __launch_bounds__(256, 2)
gemm_bf16(const bf16* __restrict__ A, const bf16* __restrict__ B,
          void* __restrict__ Cv,
          int K, int lda, int ldb, int ldc,
          int Hdiv, long sAb, long sAh, long sBb, long sBh, long sCb, long sCh,
          const float* __restrict__ xin, const float* __restrict__ bu)
{
    constexpr int APAD = 40;      // bf16 row stride, A & NT-B tiles
    constexpr int BPADNN = 136;   // bf16 row stride, NN-B tiles
    constexpr uint32_t A_STG = 128 * APAD * 2;                       // bytes/stage
    constexpr uint32_t B_STG = TRANSB ? 128u * APAD * 2 : 32u * BPADNN * 2;

    extern __shared__ __align__(16) bf16 dynsmem[];
    const uint32_t sA0 = sptr(dynsmem);
    const uint32_t sB0 = sA0 + NSTAGE * A_STG;

    const int z  = blockIdx.z;
    const int zb = z / Hdiv;
    const int zh = z % Hdiv;
    A += zb * sAb + zh * sAh;
    B += zb * sBb + zh * sBh;

    const int mBase = blockIdx.y * 128;
    const int nBase = blockIdx.x * 128;
    const int tid   = threadIdx.x;
    const int lane  = tid & 31;
    const int warp  = tid >> 5;
    const int warpM = (warp & 3) * 32;
    const int warpN = (warp >> 2) * 64;

    // per-thread gmem<->smem chunk mapping (16B chunks)
    const int u0 = tid, u1 = tid + 256;
    const int ar0 = u0 >> 2, ac0 = (u0 & 3) * 8;
    const int ar1 = u1 >> 2, ac1 = (u1 & 3) * 8;
    const int nbr0 = u0 >> 4, nbc0 = (u0 & 15) * 8;   // NN B mapping
    const int nbr1 = u1 >> 4, nbc1 = (u1 & 15) * 8;

    // ldmatrix per-lane offsets
    const int lj = lane >> 3;
    const int lr = lane & 7;
    const int aFR = (lj & 1) * 8 + lr;
    const int aFC = (lj >> 1) * 8;
    const int bNTn = lr + 8 * (lj >> 1);
    const int bNTk = 8 * (lj & 1);
    const int bNNk = lr + 8 * (lj & 1);
    const int bNNn = 8 * (lj >> 1);

    float acc[2][8][4];
    #pragma unroll
    for (int i = 0; i < 2; i++)
        #pragma unroll
        for (int j = 0; j < 8; j++)
            #pragma unroll
            for (int q = 0; q < 4; q++) acc[i][j][q] = 0.f;

    const int ntile = K >> 5;

    auto prefetch = [&](int kt, int s) {
        const uint32_t sa = sA0 + (uint32_t)s * A_STG;
        const uint32_t sb = sB0 + (uint32_t)s * B_STG;
        const int k0 = kt << 5;
        cp16(sa + (ar0 * APAD + ac0) * 2, &A[(long)(mBase + ar0) * lda + k0 + ac0]);
        cp16(sa + (ar1 * APAD + ac1) * 2, &A[(long)(mBase + ar1) * lda + k0 + ac1]);
        if (TRANSB) {
            cp16(sb + (ar0 * APAD + ac0) * 2, &B[(long)(nBase + ar0) * ldb + k0 + ac0]);
            cp16(sb + (ar1 * APAD + ac1) * 2, &B[(long)(nBase + ar1) * ldb + k0 + ac1]);
        } else {
            cp16(sb + (nbr0 * BPADNN + nbc0) * 2, &B[(long)(k0 + nbr0) * ldb + nBase + nbc0]);
            cp16(sb + (nbr1 * BPADNN + nbc1) * 2, &B[(long)(k0 + nbr1) * ldb + nBase + nbc1]);
        }
    };

    // preload NSTAGE-1 stages
    prefetch(0, 0); CP_COMMIT();
    prefetch(1, 1); CP_COMMIT();

    for (int i = 0; i < ntile; i++) {
        CP_WAIT(1);
        __syncthreads();
        {
            const int pf = i + NSTAGE - 1;
            if (pf < ntile) prefetch(pf, pf % NSTAGE);
            CP_COMMIT();
        }
        const int s = i % NSTAGE;
        const uint32_t sa = sA0 + (uint32_t)s * A_STG;
        const uint32_t sb = sB0 + (uint32_t)s * B_STG;

        #pragma unroll
        for (int kk = 0; kk < 32; kk += 16) {
            uint32_t aF[2][4];
            #pragma unroll
            for (int mt = 0; mt < 2; mt++) {
                uint32_t addr = sa + ((warpM + mt * 16 + aFR) * APAD + kk + aFC) * 2;
                ldm_x4(aF[mt][0], aF[mt][1], aF[mt][2], aF[mt][3], addr);
            }
            uint32_t bF[8][2];
            #pragma unroll
            for (int np = 0; np < 4; np++) {
                uint32_t r0, r1, r2, r3;
                if (TRANSB) {
                    uint32_t addr = sb + ((warpN + np * 16 + bNTn) * APAD + kk + bNTk) * 2;
                    ldm_x4(r0, r1, r2, r3, addr);
                } else {
                    uint32_t addr = sb + ((kk + bNNk) * BPADNN + warpN + np * 16 + bNNn) * 2;
                    ldm_x4_t(r0, r1, r2, r3, addr);
                }
                bF[np * 2][0] = r0; bF[np * 2][1] = r1;
                bF[np * 2 + 1][0] = r2; bF[np * 2 + 1][1] = r3;
            }
            #pragma unroll
            for (int mt = 0; mt < 2; mt++)
                #pragma unroll
                for (int nt = 0; nt < 8; nt++)
                    mma16816(acc[mt][nt], aF[mt], bF[nt]);
        }
    }

    // ---- epilogue ----
    const int qr = lane >> 2;
    const int qc = (lane & 3) * 2;
    #pragma unroll
    for (int mt = 0; mt < 2; mt++) {
        #pragma unroll
        for (int nt = 0; nt < 8; nt++) {
            int r0 = mBase + warpM + mt * 16 + qr;
            int r1 = r0 + 8;
            int col = nBase + warpN + nt * 8 + qc;
            float* c = acc[mt][nt];
            if (EPI == 0) {
                bf16* C = (bf16*)Cv + zb * sCb + zh * sCh;
                *reinterpret_cast<bf162*>(&C[(long)r0 * ldc + col]) =
                    __floats2bfloat162_rn(c[0], c[1]);
                *reinterpret_cast<bf162*>(&C[(long)r1 * ldc + col]) =
                    __floats2bfloat162_rn(c[2], c[3]);
            } else if (EPI == 1) {
                float* C = (float*)Cv + zb * sCb + zh * sCh;
                *reinterpret_cast<float2*>(&C[(long)r0 * ldc + col]) = make_float2(c[0], c[1]);
                *reinterpret_cast<float2*>(&C[(long)r1 * ldc + col]) = make_float2(c[2], c[3]);
            } else {
                float* C = (float*)Cv;
                float b0 = bu[col], b1 = bu[col + 1];
                long o0 = (long)r0 * CDIM + EDIM + col;
                long o1 = (long)r1 * CDIM + EDIM + col;
                C[o0]     = c[0] + b0 + xin[o0];
                C[o0 + 1] = c[1] + b1 + xin[o0 + 1];
                C[o1]     = c[2] + b0 + xin[o1];
                C[o1 + 1] = c[3] + b1 + xin[o1 + 1];
            }
        }
    }
}

// ---------------------------------------------------------------------------
// Row softmax (1024 wide, fp32 in, bf16 out). One CTA of 256 per row.
// ---------------------------------------------------------------------------
__global__ void __launch_bounds__(256)
softmax1024(const float* __restrict__ S, bf16* __restrict__ P)
{
    const float4* p4 = reinterpret_cast<const float4*>(S + (size_t)blockIdx.x * 1024);
    bf162* o2 = reinterpret_cast<bf162*>(P + (size_t)blockIdx.x * 1024);
    const int tid = threadIdx.x, lane = tid & 31, wid = tid >> 5;
    __shared__ float red[8];
    __shared__ float bcast[2];

    float4 v = p4[tid];
    float m = fmaxf(fmaxf(v.x, v.y), fmaxf(v.z, v.w));
    #pragma unroll
    for (int o = 16; o; o >>= 1) m = fmaxf(m, __shfl_xor_sync(~0u, m, o));
    if (lane == 0) red[wid] = m;
    __syncthreads();
    if (tid == 0) {
        float bm = red[0];
        #pragma unroll
        for (int i = 1; i < 8; i++) bm = fmaxf(bm, red[i]);
        bcast[0] = bm;
    }
    __syncthreads();
    const float bm = bcast[0];

    float4 e;
    e.x = __expf(v.x - bm); e.y = __expf(v.y - bm);
    e.z = __expf(v.z - bm); e.w = __expf(v.w - bm);
    float s = e.x + e.y + e.z + e.w;
    #pragma unroll
    for (int o = 16; o; o >>= 1) s += __shfl_xor_sync(~0u, s, o);
    if (lane == 0) red[wid] = s;
    __syncthreads();
    if (tid == 0) {
        float bs = 0.f;
        #pragma unroll
        for (int i = 0; i < 8; i++) bs += red[i];
        bcast[1] = 1.f / bs;
    }
    __syncthreads();
    const float r = bcast[1];
    o2[tid * 2]     = __floats2bfloat162_rn(e.x * r, e.y * r);
    o2[tid * 2 + 1] = __floats2bfloat162_rn(e.z * r, e.w * r);
}

// ---------------------------------------------------------------------------
// Conversions
// ---------------------------------------------------------------------------
__global__ void __launch_bounds__(256)
conv_x1(const float* __restrict__ x, bf16* __restrict__ dst)
{
    long idx = (long)blockIdx.x * 256 + threadIdx.x;
    long row = idx >> 6;
    int  c4  = (int)(idx & 63) * 4;
    float4 v = *reinterpret_cast<const float4*>(&x[row * CDIM + c4]);
    bf162* d = reinterpret_cast<bf162*>(&dst[row * EDIM + c4]);
    d[0] = __floats2bfloat162_rn(v.x, v.y);
    d[1] = __floats2bfloat162_rn(v.z, v.w);
}

__global__ void __launch_bounds__(256)
conv_wcat(const float* __restrict__ Wq, const float* __restrict__ Wk,
          const float* __restrict__ Wv, bf16* __restrict__ dst)
{
    long idx = (long)blockIdx.x * 256 + threadIdx.x;
    long row = idx >> 6;
    int  c4  = (int)(idx & 63) * 4;
    const float* src; float s;
    if (row < 2048)      { src = Wq + row * EDIM;          s = 0.25f; }
    else if (row < 4096) { src = Wk + (row - 2048) * EDIM; s = 0.25f; }
    else                 { src = Wv + (row - 4096) * EDIM; s = 1.0f;  }
    float4 v = *reinterpret_cast<const float4*>(&src[c4]);
    bf162* d = reinterpret_cast<bf162*>(&dst[row * EDIM + c4]);
    d[0] = __floats2bfloat162_rn(v.x * s, v.y * s);
    d[1] = __floats2bfloat162_rn(v.z * s, v.w * s);
}

__global__ void __launch_bounds__(256)
conv_wu(const float* __restrict__ Wu, bf16* __restrict__ dst)
{
    long idx = (long)blockIdx.x * 256 + threadIdx.x;
    long row = idx >> 9;
    int  c4  = (int)(idx & 511) * 4;
    float4 v = *reinterpret_cast<const float4*>(&Wu[row * HE + c4]);
    bf162* d = reinterpret_cast<bf162*>(&dst[row * HE + c4]);
    d[0] = __floats2bfloat162_rn(v.x, v.y);
    d[1] = __floats2bfloat162_rn(v.z, v.w);
}

__global__ void __launch_bounds__(256)
copy_x1(const float* __restrict__ x, float* __restrict__ out)
{
    const long idx = (long)blockIdx.x * blockDim.x + threadIdx.x;
    const long r  = idx >> 6;
    const long c4 = idx & 63;
    const float4* x4 = reinterpret_cast<const float4*>(x);
    float4* o4 = reinterpret_cast<float4*>(out);
    o4[r * 128 + c4] = x4[r * 128 + c4];
}

// ---------------------------------------------------------------------------
extern "C" void kernel_launch(void* const* d_in, const int* in_sizes, int n_in,
                              void* d_out, int out_size)
{
    const float* x  = (const float*)d_in[0];
    const float* Wq = (const float*)d_in[1];
    const float* Wk = (const float*)d_in[2];
    const float* Wv = (const float*)d_in[3];
    const float* Wu = (const float*)d_in[4];
    const float* bu = (const float*)d_in[5];
    float* out = (float*)d_out;

    bf16 *x1b, *Wcat, *Wub, *qkv, *P, *O;
    float* S;
    cudaGetSymbolAddress((void**)&x1b,  g_x1b);
    cudaGetSymbolAddress((void**)&Wcat, g_Wcat);
    cudaGetSymbolAddress((void**)&Wub,  g_Wub);
    cudaGetSymbolAddress((void**)&qkv,  g_qkv);
    cudaGetSymbolAddress((void**)&S,    g_S);
    cudaGetSymbolAddress((void**)&P,    g_P);
    cudaGetSymbolAddress((void**)&O,    g_O);

    const dim3 blk(256);
    // dynamic smem sizes (3 stages)
    const int smemNT = NSTAGE * (128 * 40 * 2) * 2;            // A + B(NT) = 61440
    const int smemNN = NSTAGE * (128 * 40 * 2 + 32 * 136 * 2); // A + B(NN) = 56832

    cudaFuncSetAttribute(gemm_bf16<0, true>,  cudaFuncAttributeMaxDynamicSharedMemorySize, smemNT);
    cudaFuncSetAttribute(gemm_bf16<1, true>,  cudaFuncAttributeMaxDynamicSharedMemorySize, smemNT);
    cudaFuncSetAttribute(gemm_bf16<2, true>,  cudaFuncAttributeMaxDynamicSharedMemorySize, smemNT);
    cudaFuncSetAttribute(gemm_bf16<0, false>, cudaFuncAttributeMaxDynamicSharedMemorySize, smemNN);

    // 0) conversions (scale folded into Wq/Wk)
    conv_x1  <<<BT * 64 / 256, blk>>>(x, x1b);
    conv_wcat<<<QKV_LD * 64 / 256, blk>>>(Wq, Wk, Wv, Wcat);
    conv_wu  <<<EDIM * 512 / 256, blk>>>(Wu, Wub);

    // 1) QKV = x1b @ Wcat^T  -> bf16 [8192, 6144]
    {
        dim3 g(QKV_LD / 128, BT / 128, 1);
        gemm_bf16<0, true><<<g, blk, smemNT>>>(x1b, Wcat, qkv, EDIM, EDIM, EDIM, QKV_LD,
                                               1, 0, 0, 0, 0, 0, 0, nullptr, nullptr);
    }
    // 2) S[b,h] = Q[b,:,h,:] @ K[b,:,h,:]^T  (fp32)
    {
        dim3 g(TNUM / 128, TNUM / 128, BNUM * HNUM);
        gemm_bf16<1, true><<<g, blk, smemNT>>>(
            qkv, qkv + HE, S, EDIM, QKV_LD, QKV_LD, TNUM,
            HNUM,
            (long)TNUM * QKV_LD, (long)EDIM,
            (long)TNUM * QKV_LD, (long)EDIM,
            (long)HNUM * TNUM * TNUM, (long)TNUM * TNUM,
            nullptr, nullptr);
    }
    // 3) P = softmax(S) -> bf16
    softmax1024<<<BNUM * HNUM * TNUM, blk>>>(S, P);

    // 4) O[b,:,h,:] = P[b,h] @ V[b,:,h,:]  (NN, bf16)
    {
        dim3 g(EDIM / 128, TNUM / 128, BNUM * HNUM);
        gemm_bf16<0, false><<<g, blk, smemNN>>>(
            P, qkv + 2 * HE, O, TNUM, TNUM, QKV_LD, HE,
            HNUM,
            (long)HNUM * TNUM * TNUM, (long)TNUM * TNUM,
            (long)TNUM * QKV_LD, (long)EDIM,
            (long)TNUM * HE, (long)EDIM,
            nullptr, nullptr);
    }
    // 5) out[:,256:] = O @ Wub^T + bu + x2
    {
        dim3 g(EDIM / 128, BT / 128, 1);
        gemm_bf16<2, true><<<g, blk, smemNT>>>(O, Wub, out, HE, HE, HE, CDIM,
                                               1, 0, 0, 0, 0, 0, 0, x, bu);
    }
    // 6) out[:,:256] = x1
    copy_x1<<<BT * 64 / 256, blk>>>(x, out);
}

// round 7
// speedup vs baseline: 6.5099x; 1.0908x over previous
#include <cuda_runtime.h>
#include <cuda_bf16.h>
#include <math.h>
#include <stdint.h>

// Problem constants
#define BNUM 8
#define TNUM 1024
#define CDIM 512
#define EDIM 256
#define HNUM 8
#define BT   8192
#define QKV_LD 6144
#define HE   2048

typedef __nv_bfloat16 bf16;
typedef __nv_bfloat162 bf162;

// Scratch (__device__ globals; no allocation allowed)
__device__ bf16  g_x1b[(long)BT * EDIM];
__device__ bf16  g_Wcat[(long)QKV_LD * EDIM];
__device__ bf16  g_Wub[(long)EDIM * HE];
__device__ bf16  g_qkv[(long)BT * QKV_LD];
__device__ bf16  g_P[(long)BNUM * HNUM * TNUM * TNUM];   // bf16 logits -> softmax in place
__device__ bf16  g_O[(long)BT * HE];

__device__ __forceinline__ uint32_t sptr(const void* p) {
    return (uint32_t)__cvta_generic_to_shared(p);
}
__device__ __forceinline__ void ldm_x4(uint32_t& r0, uint32_t& r1, uint32_t& r2,
                                       uint32_t& r3, uint32_t addr) {
    asm volatile("ldmatrix.sync.aligned.m8n8.x4.shared.b16 {%0,%1,%2,%3}, [%4];"
                 : "=r"(r0), "=r"(r1), "=r"(r2), "=r"(r3) : "r"(addr));
}
__device__ __forceinline__ void ldm_x4_t(uint32_t& r0, uint32_t& r1, uint32_t& r2,
                                         uint32_t& r3, uint32_t addr) {
    asm volatile("ldmatrix.sync.aligned.m8n8.x4.trans.shared.b16 {%0,%1,%2,%3}, [%4];"
                 : "=r"(r0), "=r"(r1), "=r"(r2), "=r"(r3) : "r"(addr));
}
__device__ __forceinline__ void mma16816(float* d, const uint32_t* a, const uint32_t* b) {
    asm volatile(
        "mma.sync.aligned.m16n8k16.row.col.f32.bf16.bf16.f32 "
        "{%0,%1,%2,%3}, {%4,%5,%6,%7}, {%8,%9}, {%0,%1,%2,%3};"
        : "+f"(d[0]), "+f"(d[1]), "+f"(d[2]), "+f"(d[3])
        : "r"(a[0]), "r"(a[1]), "r"(a[2]), "r"(a[3]), "r"(b[0]), "r"(b[1]));
}
__device__ __forceinline__ void cp16(uint32_t saddr, const void* gptr) {
    asm volatile("cp.async.cg.shared.global [%0], [%1], 16;" :: "r"(saddr), "l"(gptr));
}
#define CP_COMMIT() asm volatile("cp.async.commit_group;")
#define CP_WAIT(N)  asm volatile("cp.async.wait_group %0;" :: "n"(N))

// ---------------------------------------------------------------------------
// bf16 tensor-core GEMM, 128x128 tile, BK=32, cp.async 4-stage pipeline,
// 256 threads (8 warps, 32x64 warp tiles), 2 CTAs/SM.
// Both kk-half fragments are issued before the MMA block so the second
// half's LDSM latency hides behind the first half's 16 MMAs.
//   TRANSB=true : C = A * B^T  (B stored [N][K])
//   TRANSB=false: C = A * B    (B stored [K][N])
// EPI 0: bf16 out; EPI 2: fused residual+bias fp32 out into out[:,256:].
// ---------------------------------------------------------------------------
#define NSTAGE 4

template<int EPI, bool TRANSB>
__global__ void __launch_bounds__(256, 2)
gemm_bf16(const bf16* __restrict__ A, const bf16* __restrict__ B,
          void* __restrict__ Cv,
          int K, int lda, int ldb, int ldc,
          int Hdiv, long sAb, long sAh, long sBb, long sBh, long sCb, long sCh,
          const float* __restrict__ xin, const float* __restrict__ bu)
{
    constexpr int APAD = 40;
    constexpr int BPADNN = 136;
    constexpr uint32_t A_STG = 128 * APAD * 2;
    constexpr uint32_t B_STG = TRANSB ? 128u * APAD * 2 : 32u * BPADNN * 2;

    extern __shared__ __align__(16) bf16 dynsmem[];
    const uint32_t sA0 = sptr(dynsmem);
    const uint32_t sB0 = sA0 + NSTAGE * A_STG;

    const int z  = blockIdx.z;
    const int zb = z / Hdiv;
    const int zh = z % Hdiv;
    A += zb * sAb + zh * sAh;
    B += zb * sBb + zh * sBh;

    const int mBase = blockIdx.y * 128;
    const int nBase = blockIdx.x * 128;
    const int tid   = threadIdx.x;
    const int lane  = tid & 31;
    const int warp  = tid >> 5;
    const int warpM = (warp & 3) * 32;
    const int warpN = (warp >> 2) * 64;

    const int u0 = tid, u1 = tid + 256;
    const int ar0 = u0 >> 2, ac0 = (u0 & 3) * 8;
    const int ar1 = u1 >> 2, ac1 = (u1 & 3) * 8;
    const int nbr0 = u0 >> 4, nbc0 = (u0 & 15) * 8;
    const int nbr1 = u1 >> 4, nbc1 = (u1 & 15) * 8;

    const int lj = lane >> 3;
    const int lr = lane & 7;
    const int aFR = (lj & 1) * 8 + lr;
    const int aFC = (lj >> 1) * 8;
    const int bNTn = lr + 8 * (lj >> 1);
    const int bNTk = 8 * (lj & 1);
    const int bNNk = lr + 8 * (lj & 1);
    const int bNNn = 8 * (lj >> 1);

    float acc[2][8][4];
    #pragma unroll
    for (int i = 0; i < 2; i++)
        #pragma unroll
        for (int j = 0; j < 8; j++)
            #pragma unroll
            for (int q = 0; q < 4; q++) acc[i][j][q] = 0.f;

    const int ntile = K >> 5;

    auto prefetch = [&](int kt, int s) {
        const uint32_t sa = sA0 + (uint32_t)s * A_STG;
        const uint32_t sb = sB0 + (uint32_t)s * B_STG;
        const int k0 = kt << 5;
        cp16(sa + (ar0 * APAD + ac0) * 2, &A[(long)(mBase + ar0) * lda + k0 + ac0]);
        cp16(sa + (ar1 * APAD + ac1) * 2, &A[(long)(mBase + ar1) * lda + k0 + ac1]);
        if (TRANSB) {
            cp16(sb + (ar0 * APAD + ac0) * 2, &B[(long)(nBase + ar0) * ldb + k0 + ac0]);
            cp16(sb + (ar1 * APAD + ac1) * 2, &B[(long)(nBase + ar1) * ldb + k0 + ac1]);
        } else {
            cp16(sb + (nbr0 * BPADNN + nbc0) * 2, &B[(long)(k0 + nbr0) * ldb + nBase + nbc0]);
            cp16(sb + (nbr1 * BPADNN + nbc1) * 2, &B[(long)(k0 + nbr1) * ldb + nBase + nbc1]);
        }
    };

    // preload NSTAGE-1 stages
    prefetch(0, 0); CP_COMMIT();
    prefetch(1, 1); CP_COMMIT();
    prefetch(2, 2); CP_COMMIT();

    for (int i = 0; i < ntile; i++) {
        CP_WAIT(2);
        __syncthreads();
        {
            const int pf = i + NSTAGE - 1;
            if (pf < ntile) prefetch(pf, pf & (NSTAGE - 1));
            CP_COMMIT();
        }
        const int s = i & (NSTAGE - 1);
        const uint32_t sa = sA0 + (uint32_t)s * A_STG;
        const uint32_t sb = sB0 + (uint32_t)s * B_STG;

        // issue ALL fragment loads for both kk halves first
        uint32_t aF[2][2][4];   // [half][mt][reg]
        uint32_t bF[2][8][2];   // [half][nt][reg]
        #pragma unroll
        for (int h = 0; h < 2; h++) {
            const int kk = h * 16;
            #pragma unroll
            for (int mt = 0; mt < 2; mt++) {
                uint32_t addr = sa + ((warpM + mt * 16 + aFR) * APAD + kk + aFC) * 2;
                ldm_x4(aF[h][mt][0], aF[h][mt][1], aF[h][mt][2], aF[h][mt][3], addr);
            }
            #pragma unroll
            for (int np = 0; np < 4; np++) {
                uint32_t r0, r1, r2, r3;
                if (TRANSB) {
                    uint32_t addr = sb + ((warpN + np * 16 + bNTn) * APAD + kk + bNTk) * 2;
                    ldm_x4(r0, r1, r2, r3, addr);
                } else {
                    uint32_t addr = sb + ((kk + bNNk) * BPADNN + warpN + np * 16 + bNNn) * 2;
                    ldm_x4_t(r0, r1, r2, r3, addr);
                }
                bF[h][np * 2][0] = r0;     bF[h][np * 2][1] = r1;
                bF[h][np * 2 + 1][0] = r2; bF[h][np * 2 + 1][1] = r3;
            }
        }
        // then all MMAs (half 0 overlaps half 1's LDSM returns)
        #pragma unroll
        for (int h = 0; h < 2; h++)
            #pragma unroll
            for (int mt = 0; mt < 2; mt++)
                #pragma unroll
                for (int nt = 0; nt < 8; nt++)
                    mma16816(acc[mt][nt], aF[h][mt], bF[h][nt]);
    }

    const int qr = lane >> 2;
    const int qc = (lane & 3) * 2;
    #pragma unroll
    for (int mt = 0; mt < 2; mt++) {
        #pragma unroll
        for (int nt = 0; nt < 8; nt++) {
            int r0 = mBase + warpM + mt * 16 + qr;
            int r1 = r0 + 8;
            int col = nBase + warpN + nt * 8 + qc;
            float* c = acc[mt][nt];
            if (EPI == 0) {
                bf16* C = (bf16*)Cv + zb * sCb + zh * sCh;
                *reinterpret_cast<bf162*>(&C[(long)r0 * ldc + col]) =
                    __floats2bfloat162_rn(c[0], c[1]);
                *reinterpret_cast<bf162*>(&C[(long)r1 * ldc + col]) =
                    __floats2bfloat162_rn(c[2], c[3]);
            } else {
                float* C = (float*)Cv;
                float b0 = bu[col], b1 = bu[col + 1];
                long o0 = (long)r0 * CDIM + EDIM + col;
                long o1 = (long)r1 * CDIM + EDIM + col;
                C[o0]     = c[0] + b0 + xin[o0];
                C[o0 + 1] = c[1] + b1 + xin[o0 + 1];
                C[o1]     = c[2] + b0 + xin[o1];
                C[o1 + 1] = c[3] + b1 + xin[o1 + 1];
            }
        }
    }
}

// ---------------------------------------------------------------------------
// Warp-per-row softmax, in place on bf16 rows of 1024. 8 rows per CTA.
// ---------------------------------------------------------------------------
__global__ void __launch_bounds__(256)
softmax_bf16(bf16* __restrict__ P)
{
    const long row = (long)blockIdx.x * 8 + (threadIdx.x >> 5);
    const int lane = threadIdx.x & 31;
    uint4* p4 = reinterpret_cast<uint4*>(P + row * 1024);

    uint4 v[4];
    float f[32];
    #pragma unroll
    for (int c = 0; c < 4; c++) {
        v[c] = p4[c * 32 + lane];
        const bf162* h = reinterpret_cast<const bf162*>(&v[c]);
        #pragma unroll
        for (int q = 0; q < 4; q++) {
            float2 t = __bfloat1622float2(h[q]);
            f[c * 8 + q * 2]     = t.x;
            f[c * 8 + q * 2 + 1] = t.y;
        }
    }
    float m = f[0];
    #pragma unroll
    for (int i = 1; i < 32; i++) m = fmaxf(m, f[i]);
    #pragma unroll
    for (int o = 16; o; o >>= 1) m = fmaxf(m, __shfl_xor_sync(~0u, m, o));

    float s = 0.f;
    #pragma unroll
    for (int i = 0; i < 32; i++) { f[i] = __expf(f[i] - m); s += f[i]; }
    #pragma unroll
    for (int o = 16; o; o >>= 1) s += __shfl_xor_sync(~0u, s, o);
    const float r = 1.f / s;

    #pragma unroll
    for (int c = 0; c < 4; c++) {
        bf162* h = reinterpret_cast<bf162*>(&v[c]);
        #pragma unroll
        for (int q = 0; q < 4; q++)
            h[q] = __floats2bfloat162_rn(f[c * 8 + q * 2] * r, f[c * 8 + q * 2 + 1] * r);
        p4[c * 32 + lane] = v[c];
    }
}

// ---------------------------------------------------------------------------
// Fused: out[:, :256] = x1 (fp32 copy) AND x1b = bf16(x1)
// ---------------------------------------------------------------------------
__global__ void __launch_bounds__(256)
prep_x1(const float* __restrict__ x, float* __restrict__ out, bf16* __restrict__ x1b)
{
    long idx = (long)blockIdx.x * 256 + threadIdx.x;   // over BT*64
    long row = idx >> 6;
    int  c4  = (int)(idx & 63) * 4;
    float4 v = *reinterpret_cast<const float4*>(&x[row * CDIM + c4]);
    *reinterpret_cast<float4*>(&out[row * CDIM + c4]) = v;
    bf162* d = reinterpret_cast<bf162*>(&x1b[row * EDIM + c4]);
    d[0] = __floats2bfloat162_rn(v.x, v.y);
    d[1] = __floats2bfloat162_rn(v.z, v.w);
}

__global__ void __launch_bounds__(256)
conv_wcat(const float* __restrict__ Wq, const float* __restrict__ Wk,
          const float* __restrict__ Wv, bf16* __restrict__ dst)
{
    long idx = (long)blockIdx.x * 256 + threadIdx.x;   // over 6144*64
    long row = idx >> 6;
    int  c4  = (int)(idx & 63) * 4;
    const float* src; float s;
    if (row < 2048)      { src = Wq + row * EDIM;          s = 0.25f; }
    else if (row < 4096) { src = Wk + (row - 2048) * EDIM; s = 0.25f; }
    else                 { src = Wv + (row - 4096) * EDIM; s = 1.0f;  }
    float4 v = *reinterpret_cast<const float4*>(&src[c4]);
    bf162* d = reinterpret_cast<bf162*>(&dst[row * EDIM + c4]);
    d[0] = __floats2bfloat162_rn(v.x * s, v.y * s);
    d[1] = __floats2bfloat162_rn(v.z * s, v.w * s);
}

__global__ void __launch_bounds__(256)
conv_wu(const float* __restrict__ Wu, bf16* __restrict__ dst)
{
    long idx = (long)blockIdx.x * 256 + threadIdx.x;   // over 256*512
    long row = idx >> 9;
    int  c4  = (int)(idx & 511) * 4;
    float4 v = *reinterpret_cast<const float4*>(&Wu[row * HE + c4]);
    bf162* d = reinterpret_cast<bf162*>(&dst[row * HE + c4]);
    d[0] = __floats2bfloat162_rn(v.x, v.y);
    d[1] = __floats2bfloat162_rn(v.z, v.w);
}

// ---------------------------------------------------------------------------
extern "C" void kernel_launch(void* const* d_in, const int* in_sizes, int n_in,
                              void* d_out, int out_size)
{
    const float* x  = (const float*)d_in[0];
    const float* Wq = (const float*)d_in[1];
    const float* Wk = (const float*)d_in[2];
    const float* Wv = (const float*)d_in[3];
    const float* Wu = (const float*)d_in[4];
    const float* bu = (const float*)d_in[5];
    float* out = (float*)d_out;

    bf16 *x1b, *Wcat, *Wub, *qkv, *P, *O;
    cudaGetSymbolAddress((void**)&x1b,  g_x1b);
    cudaGetSymbolAddress((void**)&Wcat, g_Wcat);
    cudaGetSymbolAddress((void**)&Wub,  g_Wub);
    cudaGetSymbolAddress((void**)&qkv,  g_qkv);
    cudaGetSymbolAddress((void**)&P,    g_P);
    cudaGetSymbolAddress((void**)&O,    g_O);

    const dim3 blk(256);
    // dynamic smem sizes (4 stages)
    const int smemNT = NSTAGE * (128 * 40 * 2) * 2;            // 81920
    const int smemNN = NSTAGE * (128 * 40 * 2 + 32 * 136 * 2); // 75776

    cudaFuncSetAttribute(gemm_bf16<0, true>,  cudaFuncAttributeMaxDynamicSharedMemorySize, smemNT);
    cudaFuncSetAttribute(gemm_bf16<2, true>,  cudaFuncAttributeMaxDynamicSharedMemorySize, smemNT);
    cudaFuncSetAttribute(gemm_bf16<0, false>, cudaFuncAttributeMaxDynamicSharedMemorySize, smemNN);

    // 0) prep: out[:,:256]=x1, x1b=bf16(x1); weight conversions (scale folded)
    prep_x1  <<<BT * 64 / 256, blk>>>(x, out, x1b);
    conv_wcat<<<QKV_LD * 64 / 256, blk>>>(Wq, Wk, Wv, Wcat);
    conv_wu  <<<EDIM * 512 / 256, blk>>>(Wu, Wub);

    // 1) QKV = x1b @ Wcat^T  -> bf16 [8192, 6144]
    {
        dim3 g(QKV_LD / 128, BT / 128, 1);
        gemm_bf16<0, true><<<g, blk, smemNT>>>(x1b, Wcat, qkv, EDIM, EDIM, EDIM, QKV_LD,
                                               1, 0, 0, 0, 0, 0, 0, nullptr, nullptr);
    }
    // 2) S[b,h] = Q @ K^T -> bf16 logits in g_P
    {
        dim3 g(TNUM / 128, TNUM / 128, BNUM * HNUM);
        gemm_bf16<0, true><<<g, blk, smemNT>>>(
            qkv, qkv + HE, P, EDIM, QKV_LD, QKV_LD, TNUM,
            HNUM,
            (long)TNUM * QKV_LD, (long)EDIM,
            (long)TNUM * QKV_LD, (long)EDIM,
            (long)HNUM * TNUM * TNUM, (long)TNUM * TNUM,
            nullptr, nullptr);
    }
    // 3) softmax in place on g_P (warp per row)
    softmax_bf16<<<BNUM * HNUM * TNUM / 8, blk>>>(P);

    // 4) O = P @ V  (NN)
    {
        dim3 g(EDIM / 128, TNUM / 128, BNUM * HNUM);
        gemm_bf16<0, false><<<g, blk, smemNN>>>(
            P, qkv + 2 * HE, O, TNUM, TNUM, QKV_LD, HE,
            HNUM,
            (long)HNUM * TNUM * TNUM, (long)TNUM * TNUM,
            (long)TNUM * QKV_LD, (long)EDIM,
            (long)TNUM * HE, (long)EDIM,
            nullptr, nullptr);
    }
    // 5) out[:,256:] = O @ Wub^T + bu + x2  (fused epilogue)
    {
        dim3 g(EDIM / 128, BT / 128, 1);
        gemm_bf16<2, true><<<g, blk, smemNT>>>(O, Wub, out, HE, HE, HE, CDIM,
                                               1, 0, 0, 0, 0, 0, 0, x, bu);
    }
}

// round 8
// speedup vs baseline: 7.3556x; 1.1299x over previous
#include <cuda_runtime.h>
#include <cuda_bf16.h>
#include <math.h>
#include <stdint.h>

// Problem constants
#define BNUM 8
#define TNUM 1024
#define CDIM 512
#define EDIM 256
#define HNUM 8
#define BT   8192
#define QKV_LD 6144
#define HE   2048

typedef __nv_bfloat16 bf16;
typedef __nv_bfloat162 bf162;

// Scratch (__device__ globals; no allocation allowed)
__device__ bf16  g_x1b[(long)BT * EDIM];
__device__ bf16  g_Wcat[(long)QKV_LD * EDIM];
__device__ bf16  g_Wub[(long)EDIM * HE];
__device__ bf16  g_qkv[(long)BT * QKV_LD];
__device__ bf16  g_P[(long)BNUM * HNUM * TNUM * TNUM];   // bf16 logits -> softmax in place
__device__ bf16  g_O[(long)BT * HE];

__device__ __forceinline__ uint32_t sptr(const void* p) {
    return (uint32_t)__cvta_generic_to_shared(p);
}
__device__ __forceinline__ void ldm_x4(uint32_t& r0, uint32_t& r1, uint32_t& r2,
                                       uint32_t& r3, uint32_t addr) {
    asm volatile("ldmatrix.sync.aligned.m8n8.x4.shared.b16 {%0,%1,%2,%3}, [%4];"
                 : "=r"(r0), "=r"(r1), "=r"(r2), "=r"(r3) : "r"(addr));
}
__device__ __forceinline__ void ldm_x4_t(uint32_t& r0, uint32_t& r1, uint32_t& r2,
                                         uint32_t& r3, uint32_t addr) {
    asm volatile("ldmatrix.sync.aligned.m8n8.x4.trans.shared.b16 {%0,%1,%2,%3}, [%4];"
                 : "=r"(r0), "=r"(r1), "=r"(r2), "=r"(r3) : "r"(addr));
}
__device__ __forceinline__ void mma16816(float* d, const uint32_t* a, const uint32_t* b) {
    asm volatile(
        "mma.sync.aligned.m16n8k16.row.col.f32.bf16.bf16.f32 "
        "{%0,%1,%2,%3}, {%4,%5,%6,%7}, {%8,%9}, {%0,%1,%2,%3};"
        : "+f"(d[0]), "+f"(d[1]), "+f"(d[2]), "+f"(d[3])
        : "r"(a[0]), "r"(a[1]), "r"(a[2]), "r"(a[3]), "r"(b[0]), "r"(b[1]));
}
__device__ __forceinline__ void cp16(uint32_t saddr, const void* gptr) {
    asm volatile("cp.async.cg.shared.global [%0], [%1], 16;" :: "r"(saddr), "l"(gptr));
}
#define CP_COMMIT() asm volatile("cp.async.commit_group;")
#define CP_WAIT(N)  asm volatile("cp.async.wait_group %0;" :: "n"(N))

// ---------------------------------------------------------------------------
// bf16 tensor-core GEMM, 128x128 tile, BK=64, cp.async 3-stage pipeline,
// 256 threads (8 warps, 32x64 warp tiles), 2 CTAs/SM.
// One barrier per 64-K stage (half the barriers of BK=32). Fragment loads
// roll one 16-K half ahead of the MMAs (2 rolling buffers).
//   TRANSB=true : C = A * B^T  (B stored [N][K])
//   TRANSB=false: C = A * B    (B stored [K][N])
// EPI 0: bf16 out; EPI 2: fused residual+bias fp32 out into out[:,256:].
// ---------------------------------------------------------------------------
#define NSTAGE 3
#define BK 64

template<int EPI, bool TRANSB>
__global__ void __launch_bounds__(256, 2)
gemm_bf16(const bf16* __restrict__ A, const bf16* __restrict__ B,
          void* __restrict__ Cv,
          int K, int lda, int ldb, int ldc,
          int Hdiv, long sAb, long sAh, long sBb, long sBh, long sCb, long sCh,
          const float* __restrict__ xin, const float* __restrict__ bu)
{
    constexpr int APAD = 72;       // bf16 row stride for 64-wide K rows (conflict-free)
    constexpr int BPADNN = 136;    // bf16 row stride for 128-wide NN-B rows
    constexpr uint32_t A_STG = 128 * APAD * 2;                        // 18432 B
    constexpr uint32_t B_STG = TRANSB ? 128u * APAD * 2 : 64u * BPADNN * 2;

    extern __shared__ __align__(16) bf16 dynsmem[];
    const uint32_t sA0 = sptr(dynsmem);
    const uint32_t sB0 = sA0 + NSTAGE * A_STG;

    const int z  = blockIdx.z;
    const int zb = z / Hdiv;
    const int zh = z % Hdiv;
    A += zb * sAb + zh * sAh;
    B += zb * sBb + zh * sBh;

    const int mBase = blockIdx.y * 128;
    const int nBase = blockIdx.x * 128;
    const int tid   = threadIdx.x;
    const int lane  = tid & 31;
    const int warp  = tid >> 5;
    const int warpM = (warp & 3) * 32;
    const int warpN = (warp >> 2) * 64;

    // gmem<->smem 16B-chunk mapping. A tile 128x64: 1024 chunks, 4/thread.
    // chunk c: row = c>>3, col = (c&7)*8.  NN B tile 64x128: row = c>>4, col = (c&15)*8.
    const int lj = lane >> 3;
    const int lr = lane & 7;
    const int aFR = (lj & 1) * 8 + lr;
    const int aFC = (lj >> 1) * 8;
    const int bNTn = lr + 8 * (lj >> 1);
    const int bNTk = 8 * (lj & 1);
    const int bNNk = lr + 8 * (lj & 1);
    const int bNNn = 8 * (lj >> 1);

    float acc[2][8][4];
    #pragma unroll
    for (int i = 0; i < 2; i++)
        #pragma unroll
        for (int j = 0; j < 8; j++)
            #pragma unroll
            for (int q = 0; q < 4; q++) acc[i][j][q] = 0.f;

    const int ntile = K / BK;

    auto prefetch = [&](int kt, int s) {
        const uint32_t sa = sA0 + (uint32_t)s * A_STG;
        const uint32_t sb = sB0 + (uint32_t)s * B_STG;
        const int k0 = kt * BK;
        #pragma unroll
        for (int u = 0; u < 4; u++) {
            const int c = tid + u * 256;
            const int r = c >> 3, cc = (c & 7) * 8;
            cp16(sa + (r * APAD + cc) * 2, &A[(long)(mBase + r) * lda + k0 + cc]);
        }
        if (TRANSB) {
            #pragma unroll
            for (int u = 0; u < 4; u++) {
                const int c = tid + u * 256;
                const int r = c >> 3, cc = (c & 7) * 8;
                cp16(sb + (r * APAD + cc) * 2, &B[(long)(nBase + r) * ldb + k0 + cc]);
            }
        } else {
            #pragma unroll
            for (int u = 0; u < 4; u++) {
                const int c = tid + u * 256;
                const int r = c >> 4, cc = (c & 15) * 8;
                cp16(sb + (r * BPADNN + cc) * 2, &B[(long)(k0 + r) * ldb + nBase + cc]);
            }
        }
    };

    // fragment rolling buffers (one 16-K half each)
    uint32_t aF[2][2][4];   // [buf][mt][reg]
    uint32_t bF[2][8][2];   // [buf][nt][reg]

    auto ldsm_half = [&](uint32_t sa, uint32_t sb, int kk, int buf) {
        #pragma unroll
        for (int mt = 0; mt < 2; mt++) {
            uint32_t addr = sa + ((warpM + mt * 16 + aFR) * APAD + kk + aFC) * 2;
            ldm_x4(aF[buf][mt][0], aF[buf][mt][1], aF[buf][mt][2], aF[buf][mt][3], addr);
        }
        #pragma unroll
        for (int np = 0; np < 4; np++) {
            uint32_t r0, r1, r2, r3;
            if (TRANSB) {
                uint32_t addr = sb + ((warpN + np * 16 + bNTn) * APAD + kk + bNTk) * 2;
                ldm_x4(r0, r1, r2, r3, addr);
            } else {
                uint32_t addr = sb + ((kk + bNNk) * BPADNN + warpN + np * 16 + bNNn) * 2;
                ldm_x4_t(r0, r1, r2, r3, addr);
            }
            bF[buf][np * 2][0] = r0;     bF[buf][np * 2][1] = r1;
            bF[buf][np * 2 + 1][0] = r2; bF[buf][np * 2 + 1][1] = r3;
        }
    };

    auto mma_half = [&](int buf) {
        #pragma unroll
        for (int mt = 0; mt < 2; mt++)
            #pragma unroll
            for (int nt = 0; nt < 8; nt++)
                mma16816(acc[mt][nt], aF[buf][mt], bF[buf][nt]);
    };

    // preload NSTAGE-1 stages
    prefetch(0, 0); CP_COMMIT();
    prefetch(1, 1); CP_COMMIT();

    int s = 0;
    for (int i = 0; i < ntile; i++) {
        CP_WAIT(1);
        __syncthreads();
        {
            const int pf = i + NSTAGE - 1;
            if (pf < ntile) prefetch(pf, (s + NSTAGE - 1 >= NSTAGE) ? s + NSTAGE - 1 - NSTAGE
                                                                    : s + NSTAGE - 1);
            CP_COMMIT();
        }
        const uint32_t sa = sA0 + (uint32_t)s * A_STG;
        const uint32_t sb = sB0 + (uint32_t)s * B_STG;
        s = (s + 1 == NSTAGE) ? 0 : s + 1;

        // rolling: ldsm(h+1) before mma(h)
        ldsm_half(sa, sb, 0, 0);
        ldsm_half(sa, sb, 16, 1);
        mma_half(0);
        ldsm_half(sa, sb, 32, 0);
        mma_half(1);
        ldsm_half(sa, sb, 48, 1);
        mma_half(0);
        mma_half(1);
    }

    const int qr = lane >> 2;
    const int qc = (lane & 3) * 2;
    #pragma unroll
    for (int mt = 0; mt < 2; mt++) {
        #pragma unroll
        for (int nt = 0; nt < 8; nt++) {
            int r0 = mBase + warpM + mt * 16 + qr;
            int r1 = r0 + 8;
            int col = nBase + warpN + nt * 8 + qc;
            float* c = acc[mt][nt];
            if (EPI == 0) {
                bf16* C = (bf16*)Cv + zb * sCb + zh * sCh;
                *reinterpret_cast<bf162*>(&C[(long)r0 * ldc + col]) =
                    __floats2bfloat162_rn(c[0], c[1]);
                *reinterpret_cast<bf162*>(&C[(long)r1 * ldc + col]) =
                    __floats2bfloat162_rn(c[2], c[3]);
            } else {
                float* C = (float*)Cv;
                float b0 = bu[col], b1 = bu[col + 1];
                long o0 = (long)r0 * CDIM + EDIM + col;
                long o1 = (long)r1 * CDIM + EDIM + col;
                C[o0]     = c[0] + b0 + xin[o0];
                C[o0 + 1] = c[1] + b1 + xin[o0 + 1];
                C[o1]     = c[2] + b0 + xin[o1];
                C[o1 + 1] = c[3] + b1 + xin[o1 + 1];
            }
        }
    }
}

// ---------------------------------------------------------------------------
// Warp-per-row softmax, in place on bf16 rows of 1024. 8 rows per CTA.
// ---------------------------------------------------------------------------
__global__ void __launch_bounds__(256)
softmax_bf16(bf16* __restrict__ P)
{
    const long row = (long)blockIdx.x * 8 + (threadIdx.x >> 5);
    const int lane = threadIdx.x & 31;
    uint4* p4 = reinterpret_cast<uint4*>(P + row * 1024);

    uint4 v[4];
    float f[32];
    #pragma unroll
    for (int c = 0; c < 4; c++) {
        v[c] = p4[c * 32 + lane];
        const bf162* h = reinterpret_cast<const bf162*>(&v[c]);
        #pragma unroll
        for (int q = 0; q < 4; q++) {
            float2 t = __bfloat1622float2(h[q]);
            f[c * 8 + q * 2]     = t.x;
            f[c * 8 + q * 2 + 1] = t.y;
        }
    }
    float m = f[0];
    #pragma unroll
    for (int i = 1; i < 32; i++) m = fmaxf(m, f[i]);
    #pragma unroll
    for (int o = 16; o; o >>= 1) m = fmaxf(m, __shfl_xor_sync(~0u, m, o));

    float s = 0.f;
    #pragma unroll
    for (int i = 0; i < 32; i++) { f[i] = __expf(f[i] - m); s += f[i]; }
    #pragma unroll
    for (int o = 16; o; o >>= 1) s += __shfl_xor_sync(~0u, s, o);
    const float r = 1.f / s;

    #pragma unroll
    for (int c = 0; c < 4; c++) {
        bf162* h = reinterpret_cast<bf162*>(&v[c]);
        #pragma unroll
        for (int q = 0; q < 4; q++)
            h[q] = __floats2bfloat162_rn(f[c * 8 + q * 2] * r, f[c * 8 + q * 2 + 1] * r);
        p4[c * 32 + lane] = v[c];
    }
}

// ---------------------------------------------------------------------------
// Fused: out[:, :256] = x1 (fp32 copy) AND x1b = bf16(x1)
// ---------------------------------------------------------------------------
__global__ void __launch_bounds__(256)
prep_x1(const float* __restrict__ x, float* __restrict__ out, bf16* __restrict__ x1b)
{
    long idx = (long)blockIdx.x * 256 + threadIdx.x;   // over BT*64
    long row = idx >> 6;
    int  c4  = (int)(idx & 63) * 4;
    float4 v = *reinterpret_cast<const float4*>(&x[row * CDIM + c4]);
    *reinterpret_cast<float4*>(&out[row * CDIM + c4]) = v;
    bf162* d = reinterpret_cast<bf162*>(&x1b[row * EDIM + c4]);
    d[0] = __floats2bfloat162_rn(v.x, v.y);
    d[1] = __floats2bfloat162_rn(v.z, v.w);
}

__global__ void __launch_bounds__(256)
conv_wcat(const float* __restrict__ Wq, const float* __restrict__ Wk,
          const float* __restrict__ Wv, bf16* __restrict__ dst)
{
    long idx = (long)blockIdx.x * 256 + threadIdx.x;   // over 6144*64
    long row = idx >> 6;
    int  c4  = (int)(idx & 63) * 4;
    const float* src; float s;
    if (row < 2048)      { src = Wq + row * EDIM;          s = 0.25f; }
    else if (row < 4096) { src = Wk + (row - 2048) * EDIM; s = 0.25f; }
    else                 { src = Wv + (row - 4096) * EDIM; s = 1.0f;  }
    float4 v = *reinterpret_cast<const float4*>(&src[c4]);
    bf162* d = reinterpret_cast<bf162*>(&dst[row * EDIM + c4]);
    d[0] = __floats2bfloat162_rn(v.x * s, v.y * s);
    d[1] = __floats2bfloat162_rn(v.z * s, v.w * s);
}

__global__ void __launch_bounds__(256)
conv_wu(const float* __restrict__ Wu, bf16* __restrict__ dst)
{
    long idx = (long)blockIdx.x * 256 + threadIdx.x;   // over 256*512
    long row = idx >> 9;
    int  c4  = (int)(idx & 511) * 4;
    float4 v = *reinterpret_cast<const float4*>(&Wu[row * HE + c4]);
    bf162* d = reinterpret_cast<bf162*>(&dst[row * HE + c4]);
    d[0] = __floats2bfloat162_rn(v.x, v.y);
    d[1] = __floats2bfloat162_rn(v.z, v.w);
}

// ---------------------------------------------------------------------------
extern "C" void kernel_launch(void* const* d_in, const int* in_sizes, int n_in,
                              void* d_out, int out_size)
{
    const float* x  = (const float*)d_in[0];
    const float* Wq = (const float*)d_in[1];
    const float* Wk = (const float*)d_in[2];
    const float* Wv = (const float*)d_in[3];
    const float* Wu = (const float*)d_in[4];
    const float* bu = (const float*)d_in[5];
    float* out = (float*)d_out;

    bf16 *x1b, *Wcat, *Wub, *qkv, *P, *O;
    cudaGetSymbolAddress((void**)&x1b,  g_x1b);
    cudaGetSymbolAddress((void**)&Wcat, g_Wcat);
    cudaGetSymbolAddress((void**)&Wub,  g_Wub);
    cudaGetSymbolAddress((void**)&qkv,  g_qkv);
    cudaGetSymbolAddress((void**)&P,    g_P);
    cudaGetSymbolAddress((void**)&O,    g_O);

    const dim3 blk(256);
    // dynamic smem: 3 stages of (A 18432 + B stage)
    const int smemNT = NSTAGE * (128 * 72 * 2) * 2;                 // 110592
    const int smemNN = NSTAGE * (128 * 72 * 2 + 64 * 136 * 2);      // 107520

    cudaFuncSetAttribute(gemm_bf16<0, true>,  cudaFuncAttributeMaxDynamicSharedMemorySize, smemNT);
    cudaFuncSetAttribute(gemm_bf16<2, true>,  cudaFuncAttributeMaxDynamicSharedMemorySize, smemNT);
    cudaFuncSetAttribute(gemm_bf16<0, false>, cudaFuncAttributeMaxDynamicSharedMemorySize, smemNN);

    // 0) prep: out[:,:256]=x1, x1b=bf16(x1); weight conversions (scale folded)
    prep_x1  <<<BT * 64 / 256, blk>>>(x, out, x1b);
    conv_wcat<<<QKV_LD * 64 / 256, blk>>>(Wq, Wk, Wv, Wcat);
    conv_wu  <<<EDIM * 512 / 256, blk>>>(Wu, Wub);

    // 1) QKV = x1b @ Wcat^T  -> bf16 [8192, 6144]
    {
        dim3 g(QKV_LD / 128, BT / 128, 1);
        gemm_bf16<0, true><<<g, blk, smemNT>>>(x1b, Wcat, qkv, EDIM, EDIM, EDIM, QKV_LD,
                                               1, 0, 0, 0, 0, 0, 0, nullptr, nullptr);
    }
    // 2) S[b,h] = Q @ K^T -> bf16 logits in g_P
    {
        dim3 g(TNUM / 128, TNUM / 128, BNUM * HNUM);
        gemm_bf16<0, true><<<g, blk, smemNT>>>(
            qkv, qkv + HE, P, EDIM, QKV_LD, QKV_LD, TNUM,
            HNUM,
            (long)TNUM * QKV_LD, (long)EDIM,
            (long)TNUM * QKV_LD, (long)EDIM,
            (long)HNUM * TNUM * TNUM, (long)TNUM * TNUM,
            nullptr, nullptr);
    }
    // 3) softmax in place on g_P (warp per row)
    softmax_bf16<<<BNUM * HNUM * TNUM / 8, blk>>>(P);

    // 4) O = P @ V  (NN)
    {
        dim3 g(EDIM / 128, TNUM / 128, BNUM * HNUM);
        gemm_bf16<0, false><<<g, blk, smemNN>>>(
            P, qkv + 2 * HE, O, TNUM, TNUM, QKV_LD, HE,
            HNUM,
            (long)HNUM * TNUM * TNUM, (long)TNUM * TNUM,
            (long)TNUM * QKV_LD, (long)EDIM,
            (long)TNUM * HE, (long)EDIM,
            nullptr, nullptr);
    }
    // 5) out[:,256:] = O @ Wub^T + bu + x2  (fused epilogue)
    {
        dim3 g(EDIM / 128, BT / 128, 1);
        gemm_bf16<2, true><<<g, blk, smemNT>>>(O, Wub, out, HE, HE, HE, CDIM,
                                               1, 0, 0, 0, 0, 0, 0, x, bu);
    }
}